// round 1
// baseline (speedup 1.0000x reference)
#include <cuda_runtime.h>
#include <cuda_bf16.h>
#include <math.h>

#define N_SEQ  4096
#define SIZE_K 8192
#define HALF_K 4096

#define BM 128
#define BN 128
#define BK 16
#define TPB 256

// ---------------- scratch (static device globals; no runtime alloc) ----------
__device__ float gK[(size_t)N_SEQ * HALF_K];   // x @ Wk + bk
__device__ float gV[(size_t)N_SEQ * HALF_K];   // x @ Wv + bv  (also q)
__device__ float gS[(size_t)N_SEQ * N_SEQ];    // (V @ K^T) / 90

__device__ __forceinline__ float* bufptr(int s) {
    return (s == 0) ? gK : ((s == 1) ? gV : gS);
}

// ---------------- SGEMM: C = alpha * A*B(^T) + bias --------------------------
// A: [M,K] row-major. TB=0: B [K,N] row-major. TB=1: B [N,K] row-major (B^T).
// ASEL/BSEL/CSEL: -1 = use external pointer, else scratch buffer id.
template<bool TB, int ASEL, int BSEL, int CSEL>
__global__ __launch_bounds__(TPB, 2)
void gemm_kernel(const float* __restrict__ Ap, const float* __restrict__ Bp,
                 const float* __restrict__ bias,
                 int M, int N, int K, float alpha)
{
    const float* __restrict__ A = (ASEL < 0) ? Ap : (const float*)bufptr(ASEL);
    const float* __restrict__ B = (BSEL < 0) ? Bp : (const float*)bufptr(BSEL);
    float* __restrict__ C = bufptr(CSEL);

    __shared__ float As[BK][BM];
    __shared__ float Bs[BK][BN];

    const int tid = threadIdx.x;
    const int bm  = blockIdx.y * BM;
    const int bn  = blockIdx.x * BN;
    const int tx  = tid & 15;   // n direction (8 cols each)
    const int ty  = tid >> 4;   // m direction (8 rows each)

    float acc[8][8];
    #pragma unroll
    for (int i = 0; i < 8; i++)
        #pragma unroll
        for (int j = 0; j < 8; j++) acc[i][j] = 0.0f;

    for (int k0 = 0; k0 < K; k0 += BK) {
        // ---- load A tile 128x16, store transposed As[k][m]
        #pragma unroll
        for (int i = 0; i < 2; i++) {
            int id = tid + i * TPB;          // 0..511
            int r  = id >> 2;                // m row 0..127
            int c4 = id & 3;                 // k float4 0..3
            float4 a = *(const float4*)(A + (size_t)(bm + r) * K + k0 + c4 * 4);
            As[c4 * 4 + 0][r] = a.x;
            As[c4 * 4 + 1][r] = a.y;
            As[c4 * 4 + 2][r] = a.z;
            As[c4 * 4 + 3][r] = a.w;
        }
        // ---- load B tile
        if (!TB) {
            #pragma unroll
            for (int i = 0; i < 2; i++) {
                int id = tid + i * TPB;      // 0..511
                int r  = id >> 5;            // k row 0..15
                int c4 = id & 31;            // n float4 0..31
                float4 b = *(const float4*)(B + (size_t)(k0 + r) * N + bn + c4 * 4);
                *(float4*)(&Bs[r][c4 * 4]) = b;
            }
        } else {
            #pragma unroll
            for (int i = 0; i < 2; i++) {
                int id = tid + i * TPB;
                int r  = id >> 2;            // n row 0..127
                int c4 = id & 3;             // k float4 0..3
                float4 b = *(const float4*)(B + (size_t)(bn + r) * K + k0 + c4 * 4);
                Bs[c4 * 4 + 0][r] = b.x;
                Bs[c4 * 4 + 1][r] = b.y;
                Bs[c4 * 4 + 2][r] = b.z;
                Bs[c4 * 4 + 3][r] = b.w;
            }
        }
        __syncthreads();

        #pragma unroll
        for (int k = 0; k < BK; k++) {
            float af[8], bf[8];
            *(float4*)&af[0] = *(const float4*)&As[k][ty * 8];
            *(float4*)&af[4] = *(const float4*)&As[k][ty * 8 + 4];
            *(float4*)&bf[0] = *(const float4*)&Bs[k][tx * 8];
            *(float4*)&bf[4] = *(const float4*)&Bs[k][tx * 8 + 4];
            #pragma unroll
            for (int i = 0; i < 8; i++)
                #pragma unroll
                for (int j = 0; j < 8; j++)
                    acc[i][j] = fmaf(af[i], bf[j], acc[i][j]);
        }
        __syncthreads();
    }

    // ---- epilogue
    #pragma unroll
    for (int i = 0; i < 8; i++) {
        size_t m = (size_t)(bm + ty * 8 + i);
        #pragma unroll
        for (int j = 0; j < 8; j += 4) {
            int n = bn + tx * 8 + j;
            float4 r;
            r.x = acc[i][j + 0] * alpha;
            r.y = acc[i][j + 1] * alpha;
            r.z = acc[i][j + 2] * alpha;
            r.w = acc[i][j + 3] * alpha;
            if (bias) {
                r.x += bias[n + 0];
                r.y += bias[n + 1];
                r.z += bias[n + 2];
                r.w += bias[n + 3];
            }
            *(float4*)(C + m * (size_t)N + n) = r;
        }
    }
}

// ---------------- fast exp on the FMA pipe (no MUFU) -------------------------
// exp(x) = 2^(x*log2e); range reduce to f in [-0.5,0.5], degree-5 poly.
// rel err ~2e-6. Clamp x >= -87 so the 2^i scale stays a normal float.
__device__ __forceinline__ float fast_exp(float x) {
    x = fmaxf(x, -87.0f);
    const float L2E = 1.4426950408889634f;
    float t = x * L2E;
    float z = t + 12582912.0f;          // round-to-nearest-int magic (2^23 * 1.5)
    float n = z - 12582912.0f;
    float f = t - n;                    // f in [-0.5, 0.5]
    int   i = __float_as_int(z) - 0x4B400000;  // = (int)n
    // 2^f Taylor poly, degree 5
    float p = 1.3333558146e-3f;
    p = fmaf(p, f, 9.6181291076e-3f);
    p = fmaf(p, f, 5.5504108665e-2f);
    p = fmaf(p, f, 2.4022650696e-1f);
    p = fmaf(p, f, 6.9314718056e-1f);
    p = fmaf(p, f, 1.0f);
    float sc = __int_as_float((i + 127) << 23);
    return p * sc;
}

// combine two online-softmax/argmax partials
__device__ __forceinline__ void combine(float& m, float& Z, float& c, int& bi,
                                        float m2, float Z2, float c2, int bi2) {
    float M  = fmaxf(m, m2);
    float r1 = fast_exp(m  - M);
    float r2 = fast_exp(m2 - M);
    Z = Z * r1 + Z2 * r2;
    float ca = c  * r1;
    float cb = c2 * r2;
    if (cb > ca || (cb == ca && bi2 < bi)) { c = cb; bi = bi2; }
    else                                   { c = ca; }
    m = M;
}

// ---------------- fused softmax + elementwise combine + max/argmax -----------
// result[i,j] = softmax(S[i,:])[j] * V[i,j];  out[i]=max_j, out[N+i]=argmax_j
__global__ __launch_bounds__(TPB)
void softmax_combine_kernel(float* __restrict__ out)
{
    const int row = blockIdx.x;
    const float4* __restrict__ S4 = (const float4*)(gS + (size_t)row * N_SEQ);
    const float4* __restrict__ V4 = (const float4*)(gV + (size_t)row * N_SEQ);
    const int tid = threadIdx.x;

    float m = -INFINITY, Z = 0.0f, c = -INFINITY;
    int bi = 0;

    #pragma unroll
    for (int it = 0; it < 4; it++) {
        int q = tid + it * TPB;          // float4 index 0..1023
        float4 s4 = S4[q];
        float4 v4 = V4[q];
        float ss[4] = {s4.x, s4.y, s4.z, s4.w};
        float vv[4] = {v4.x, v4.y, v4.z, v4.w};
        #pragma unroll
        for (int l = 0; l < 4; l++) {
            float s = ss[l];
            int   j = q * 4 + l;
            if (s > m) {
                float r = fast_exp(m - s);   // rescale old state to new max
                Z = Z * r + 1.0f;
                c = c * r;
                float cand = vv[l];          // e = 1 at the new max
                if (cand > c || (cand == c && j < bi)) { c = cand; bi = j; }
                m = s;
            } else {
                float e = fast_exp(s - m);
                Z += e;
                float cand = e * vv[l];
                if (cand > c || (cand == c && j < bi)) { c = cand; bi = j; }
            }
        }
    }

    // warp reduce
    const unsigned full = 0xffffffffu;
    #pragma unroll
    for (int off = 16; off > 0; off >>= 1) {
        float m2 = __shfl_down_sync(full, m, off);
        float Z2 = __shfl_down_sync(full, Z, off);
        float c2 = __shfl_down_sync(full, c, off);
        int   b2 = __shfl_down_sync(full, bi, off);
        combine(m, Z, c, bi, m2, Z2, c2, b2);
    }

    __shared__ float sm[8], sz[8], sc[8];
    __shared__ int   sb[8];
    int wid = tid >> 5, lane = tid & 31;
    if (lane == 0) { sm[wid] = m; sz[wid] = Z; sc[wid] = c; sb[wid] = bi; }
    __syncthreads();
    if (tid == 0) {
        #pragma unroll
        for (int w = 1; w < 8; w++)
            combine(m, Z, c, bi, sm[w], sz[w], sc[w], sb[w]);
        out[row]          = c / Z;       // max of att * V
        out[N_SEQ + row]  = (float)bi;   // argmax
    }
}

// ---------------- launch ------------------------------------------------------
extern "C" void kernel_launch(void* const* d_in, const int* in_sizes, int n_in,
                              void* d_out, int out_size)
{
    const float* x  = (const float*)d_in[0];
    const float* Wk = (const float*)d_in[1];
    const float* bk = (const float*)d_in[2];
    const float* Wv = (const float*)d_in[3];
    const float* bv = (const float*)d_in[4];
    // d_in[5] (Wq), d_in[6] (bq) are dead code in the reference (x_q = x@Wv+bv)
    float* out = (float*)d_out;

    dim3 blk(TPB);
    dim3 grid_proj(HALF_K / BN, N_SEQ / BM);   // 32 x 32
    dim3 grid_sc  (N_SEQ  / BN, N_SEQ / BM);   // 32 x 32

    // K = x @ Wk + bk
    gemm_kernel<false, -1, -1, 0><<<grid_proj, blk>>>(x, Wk, bk, N_SEQ, HALF_K, SIZE_K, 1.0f);
    // V = x @ Wv + bv  (also serves as q)
    gemm_kernel<false, -1, -1, 1><<<grid_proj, blk>>>(x, Wv, bv, N_SEQ, HALF_K, SIZE_K, 1.0f);
    // S = (V @ K^T) / 90   (SCALE = float(int(sqrt(8192))) = 90)
    gemm_kernel<true, 1, 0, 2><<<grid_sc, blk>>>(nullptr, nullptr, nullptr,
                                                 N_SEQ, N_SEQ, HALF_K, 1.0f / 90.0f);
    // softmax + elementwise V + row max/argmax
    softmax_combine_kernel<<<N_SEQ, blk>>>(out);
}

// round 3
// speedup vs baseline: 3.4371x; 3.4371x over previous
#include <cuda_runtime.h>
#include <cuda_bf16.h>
#include <math.h>
#include <stdint.h>

#define N_SEQ  4096
#define SIZE_K 8192
#define HALF_K 4096

#define BM   128
#define BN   128
#define BKC  64          // K elements per pipeline chunk (128 bytes bf16)
#define GT   256         // threads per GEMM CTA (8 warps)

// ---------------- scratch (static device globals; no runtime alloc) ----------
__device__ __nv_bfloat16 g_xh[(size_t)N_SEQ * SIZE_K];
__device__ __nv_bfloat16 g_xl[(size_t)N_SEQ * SIZE_K];
__device__ __nv_bfloat16 g_wkh[(size_t)HALF_K * SIZE_K];   // Wk^T hi  [4096,8192]
__device__ __nv_bfloat16 g_wkl[(size_t)HALF_K * SIZE_K];
__device__ __nv_bfloat16 g_wvh[(size_t)HALF_K * SIZE_K];
__device__ __nv_bfloat16 g_wvl[(size_t)HALF_K * SIZE_K];
__device__ __nv_bfloat16 g_kh[(size_t)N_SEQ * HALF_K];     // K split
__device__ __nv_bfloat16 g_kl[(size_t)N_SEQ * HALF_K];
__device__ __nv_bfloat16 g_vh[(size_t)N_SEQ * HALF_K];     // V split
__device__ __nv_bfloat16 g_vl[(size_t)N_SEQ * HALF_K];
__device__ float         g_v [(size_t)N_SEQ * HALF_K];     // V fp32
__device__ float         g_s [(size_t)N_SEQ * N_SEQ];      // scores fp32

// ---------------- PTX helpers (base sm_103 features only) --------------------
static __device__ __forceinline__ uint32_t smem_u32(const void* p) {
    uint32_t a;
    asm("{ .reg .u64 t; cvta.to.shared.u64 t, %1; cvt.u32.u64 %0, t; }" : "=r"(a) : "l"(p));
    return a;
}
static __device__ __forceinline__ void cp16(uint32_t s, const void* g) {
    asm volatile("cp.async.cg.shared.global [%0], [%1], 16;" :: "r"(s), "l"(g));
}
static __device__ __forceinline__ void cp_commit() {
    asm volatile("cp.async.commit_group;" ::: "memory");
}
template<int NP> static __device__ __forceinline__ void cp_wait() {
    asm volatile("cp.async.wait_group %0;" :: "n"(NP) : "memory");
}
static __device__ __forceinline__ void ldsm4(uint32_t* r, uint32_t addr) {
    asm volatile("ldmatrix.sync.aligned.m8n8.x4.shared.b16 {%0,%1,%2,%3}, [%4];"
        : "=r"(r[0]), "=r"(r[1]), "=r"(r[2]), "=r"(r[3]) : "r"(addr));
}
static __device__ __forceinline__ void mma16816(float* c, const uint32_t* a, const uint32_t* b) {
    asm volatile(
        "mma.sync.aligned.m16n8k16.row.col.f32.bf16.bf16.f32 "
        "{%0,%1,%2,%3}, {%4,%5,%6,%7}, {%8,%9}, {%0,%1,%2,%3};"
        : "+f"(c[0]), "+f"(c[1]), "+f"(c[2]), "+f"(c[3])
        : "r"(a[0]), "r"(a[1]), "r"(a[2]), "r"(a[3]), "r"(b[0]), "r"(b[1]));
}
static __device__ __forceinline__ void split2(float x0, float x1, uint32_t& h, uint32_t& l) {
    __nv_bfloat16 h0 = __float2bfloat16(x0), h1 = __float2bfloat16(x1);
    __nv_bfloat16 l0 = __float2bfloat16(x0 - __bfloat162float(h0));
    __nv_bfloat16 l1 = __float2bfloat16(x1 - __bfloat162float(h1));
    h = (uint32_t)__bfloat16_as_ushort(h0) | ((uint32_t)__bfloat16_as_ushort(h1) << 16);
    l = (uint32_t)__bfloat16_as_ushort(l0) | ((uint32_t)__bfloat16_as_ushort(l1) << 16);
}

// ---------------- convert / split kernels ------------------------------------
__global__ __launch_bounds__(256)
void convert_x_kernel(const float* __restrict__ x)
{
    const size_t total4 = (size_t)N_SEQ * SIZE_K / 4;
    __nv_bfloat162* xh2 = reinterpret_cast<__nv_bfloat162*>(g_xh);
    __nv_bfloat162* xl2 = reinterpret_cast<__nv_bfloat162*>(g_xl);
    for (size_t i = (size_t)blockIdx.x * blockDim.x + threadIdx.x; i < total4;
         i += (size_t)gridDim.x * blockDim.x) {
        float4 v = reinterpret_cast<const float4*>(x)[i];
        __nv_bfloat16 h0 = __float2bfloat16(v.x), h1 = __float2bfloat16(v.y);
        __nv_bfloat16 h2 = __float2bfloat16(v.z), h3 = __float2bfloat16(v.w);
        __nv_bfloat16 l0 = __float2bfloat16(v.x - __bfloat162float(h0));
        __nv_bfloat16 l1 = __float2bfloat16(v.y - __bfloat162float(h1));
        __nv_bfloat16 l2 = __float2bfloat16(v.z - __bfloat162float(h2));
        __nv_bfloat16 l3 = __float2bfloat16(v.w - __bfloat162float(h3));
        xh2[2 * i]     = __nv_bfloat162(h0, h1);
        xh2[2 * i + 1] = __nv_bfloat162(h2, h3);
        xl2[2 * i]     = __nv_bfloat162(l0, l1);
        xl2[2 * i + 1] = __nv_bfloat162(l2, l3);
    }
}

// W [SIZE_K, HALF_K] fp32 -> WT hi/lo [HALF_K, SIZE_K] bf16
template<int WSEL>
__global__ __launch_bounds__(256)
void transpose_split_kernel(const float* __restrict__ W)
{
    __nv_bfloat16* dh = (WSEL == 0) ? g_wkh : g_wvh;
    __nv_bfloat16* dl = (WSEL == 0) ? g_wkl : g_wvl;
    __shared__ float t[32][33];
    int n0 = blockIdx.x * 32;
    int k0 = blockIdx.y * 32;
    int tx = threadIdx.x, ty = threadIdx.y;   // block (32, 8)
    #pragma unroll
    for (int i = 0; i < 4; i++)
        t[ty + i * 8][tx] = W[(size_t)(k0 + ty + i * 8) * HALF_K + n0 + tx];
    __syncthreads();
    #pragma unroll
    for (int i = 0; i < 4; i++) {
        int n = n0 + ty + i * 8;
        int k = k0 + tx;
        float v = t[tx][ty + i * 8];
        __nv_bfloat16 h = __float2bfloat16(v);
        __nv_bfloat16 l = __float2bfloat16(v - __bfloat162float(h));
        dh[(size_t)n * SIZE_K + k] = h;
        dl[(size_t)n * SIZE_K + k] = l;
    }
}

// ---------------- HMMA split-bf16 GEMM ---------------------------------------
// MODE 0: K proj  (A=x, B=Wk^T, out: g_kh/g_kl,     bias=bk, K=8192)
// MODE 1: V proj  (A=x, B=Wv^T, out: g_v,g_vh/g_vl, bias=bv, K=8192)
// MODE 2: scores  (A=V, B=K,    out: g_s,           alpha=1/90, K=4096)
//
// smem stage (64 KB): Ah[128][64] | Al | Bh[128][64] | Bl, 16 KB each,
// 128B rows with SW128 xor swizzle. Two stages, cp.async double buffer.
#define STG_BYTES 65536u
#define SMEM_BYTES (2 * STG_BYTES)

template<int MODE>
__global__ __launch_bounds__(GT, 1)
void gemm3_kernel(const float* __restrict__ bias)
{
    const __nv_bfloat16 *Ah, *Al, *Bh, *Bl;
    int Ktot;
    if (MODE == 0)      { Ah = g_xh; Al = g_xl; Bh = g_wkh; Bl = g_wkl; Ktot = SIZE_K; }
    else if (MODE == 1) { Ah = g_xh; Al = g_xl; Bh = g_wvh; Bl = g_wvl; Ktot = SIZE_K; }
    else                { Ah = g_vh; Al = g_vl; Bh = g_kh;  Bl = g_kl;  Ktot = HALF_K; }

    extern __shared__ char smem[];
    const uint32_t sb = smem_u32(smem);
    const int tid  = threadIdx.x;
    const int wid  = tid >> 5;
    const int lane = tid & 31;
    const int wm   = wid & 3;     // warp row 0..3  (32 rows each)
    const int wn   = wid >> 2;    // warp col 0..1  (64 cols each)

    const int bm = blockIdx.x * BM;
    const int bn = blockIdx.y * BN;

    float acc[2][8][4];
    #pragma unroll
    for (int t = 0; t < 2; t++)
        #pragma unroll
        for (int n = 0; n < 8; n++)
            #pragma unroll
            for (int q = 0; q < 4; q++) acc[t][n][q] = 0.0f;

    const int nch = Ktot / BKC;

    auto load_chunk = [&](int ch) {
        const uint32_t stg = sb + (uint32_t)(ch & 1) * STG_BYTES;
        const size_t k0 = (size_t)ch * BKC;
        #pragma unroll
        for (int i = 0; i < 4; i++) {
            int pos = tid + i * GT;            // 0..1023
            int row = pos >> 3, seg = pos & 7;
            uint32_t soff = row * 128 + ((seg ^ (row & 7)) << 4);
            size_t ga = (size_t)(bm + row) * Ktot + k0 + seg * 8;
            size_t gb = (size_t)(bn + row) * Ktot + k0 + seg * 8;
            cp16(stg +      0 + soff, Ah + ga);
            cp16(stg + 16384u + soff, Al + ga);
            cp16(stg + 32768u + soff, Bh + gb);
            cp16(stg + 49152u + soff, Bl + gb);
        }
        cp_commit();
    };

    load_chunk(0);

    for (int ch = 0; ch < nch; ++ch) {
        if (ch + 1 < nch) { load_chunk(ch + 1); cp_wait<1>(); }
        else              { cp_wait<0>(); }
        __syncthreads();

        const uint32_t stg = sb + (uint32_t)(ch & 1) * STG_BYTES;
        #pragma unroll
        for (int k16 = 0; k16 < 4; ++k16) {
            uint32_t afh[2][4], afl[2][4];
            #pragma unroll
            for (int t = 0; t < 2; ++t) {
                int row = wm * 32 + t * 16 + (lane & 15);
                int seg = k16 * 2 + (lane >> 4);
                uint32_t off = row * 128 + ((seg ^ (row & 7)) << 4);
                ldsm4(afh[t], stg + off);
                ldsm4(afl[t], stg + 16384u + off);
            }
            uint32_t bfh[4][4], bfl[4][4];
            #pragma unroll
            for (int p = 0; p < 4; ++p) {
                int row = wn * 64 + p * 16 + ((lane >> 4) << 3) + (lane & 7);
                int seg = k16 * 2 + ((lane >> 3) & 1);
                uint32_t off = row * 128 + ((seg ^ (row & 7)) << 4);
                ldsm4(bfh[p], stg + 32768u + off);
                ldsm4(bfl[p], stg + 49152u + off);
            }
            #pragma unroll
            for (int t = 0; t < 2; ++t)
                #pragma unroll
                for (int nt = 0; nt < 8; ++nt) {
                    const uint32_t* bh = &bfh[nt >> 1][(nt & 1) * 2];
                    const uint32_t* bl = &bfl[nt >> 1][(nt & 1) * 2];
                    mma16816(acc[t][nt], afh[t], bh);   // hi*hi
                    mma16816(acc[t][nt], afh[t], bl);   // hi*lo
                    mma16816(acc[t][nt], afl[t], bh);   // lo*hi
                }
        }
        __syncthreads();
    }

    // ---- epilogue: mma C frag: c0,c1 @ (row, col..col+1), c2,c3 @ (row+8)
    #pragma unroll
    for (int t = 0; t < 2; ++t) {
        #pragma unroll
        for (int nt = 0; nt < 8; ++nt) {
            float* c = acc[t][nt];
            const int n  = bn + wn * 64 + nt * 8 + (lane & 3) * 2;
            const int m0 = bm + wm * 32 + t * 16 + (lane >> 2);
            if (MODE == 2) {
                const float a = 1.0f / 90.0f;
                *(float2*)&g_s[(size_t)m0 * N_SEQ + n]       = make_float2(c[0] * a, c[1] * a);
                *(float2*)&g_s[(size_t)(m0 + 8) * N_SEQ + n] = make_float2(c[2] * a, c[3] * a);
            } else {
                float b0 = __ldg(&bias[n]), b1 = __ldg(&bias[n + 1]);
                float x0 = c[0] + b0, x1 = c[1] + b1;
                float y0 = c[2] + b0, y1 = c[3] + b1;
                if (MODE == 1) {
                    *(float2*)&g_v[(size_t)m0 * HALF_K + n]       = make_float2(x0, x1);
                    *(float2*)&g_v[(size_t)(m0 + 8) * HALF_K + n] = make_float2(y0, y1);
                }
                __nv_bfloat16* dsth = (MODE == 0) ? g_kh : g_vh;
                __nv_bfloat16* dstl = (MODE == 0) ? g_kl : g_vl;
                uint32_t h, l;
                split2(x0, x1, h, l);
                *(uint32_t*)&dsth[(size_t)m0 * HALF_K + n] = h;
                *(uint32_t*)&dstl[(size_t)m0 * HALF_K + n] = l;
                split2(y0, y1, h, l);
                *(uint32_t*)&dsth[(size_t)(m0 + 8) * HALF_K + n] = h;
                *(uint32_t*)&dstl[(size_t)(m0 + 8) * HALF_K + n] = l;
            }
        }
    }
}

// ---------------- fast exp on the FMA pipe (no MUFU) -------------------------
__device__ __forceinline__ float fast_exp(float x) {
    x = fmaxf(x, -87.0f);
    const float L2E = 1.4426950408889634f;
    float t = x * L2E;
    float z = t + 12582912.0f;
    float n = z - 12582912.0f;
    float f = t - n;
    int   i = __float_as_int(z) - 0x4B400000;
    float p = 1.3333558146e-3f;
    p = fmaf(p, f, 9.6181291076e-3f);
    p = fmaf(p, f, 5.5504108665e-2f);
    p = fmaf(p, f, 2.4022650696e-1f);
    p = fmaf(p, f, 6.9314718056e-1f);
    p = fmaf(p, f, 1.0f);
    float sc = __int_as_float((i + 127) << 23);
    return p * sc;
}

__device__ __forceinline__ void combine(float& m, float& Z, float& c, int& bi,
                                        float m2, float Z2, float c2, int bi2) {
    float M  = fmaxf(m, m2);
    float r1 = fast_exp(m  - M);
    float r2 = fast_exp(m2 - M);
    Z = Z * r1 + Z2 * r2;
    float ca = c  * r1;
    float cb = c2 * r2;
    if (cb > ca || (cb == ca && bi2 < bi)) { c = cb; bi = bi2; }
    else                                   { c = ca; }
    m = M;
}

__global__ __launch_bounds__(256)
void softmax_combine_kernel(float* __restrict__ out)
{
    const int row = blockIdx.x;
    const float4* __restrict__ S4 = (const float4*)(g_s + (size_t)row * N_SEQ);
    const float4* __restrict__ V4 = (const float4*)(g_v + (size_t)row * N_SEQ);
    const int tid = threadIdx.x;

    float m = -INFINITY, Z = 0.0f, c = -INFINITY;
    int bi = 0;

    #pragma unroll
    for (int it = 0; it < 4; it++) {
        int q = tid + it * 256;
        float4 s4 = S4[q];
        float4 v4 = V4[q];
        float ss[4] = {s4.x, s4.y, s4.z, s4.w};
        float vv[4] = {v4.x, v4.y, v4.z, v4.w};
        #pragma unroll
        for (int l = 0; l < 4; l++) {
            float s = ss[l];
            int   j = q * 4 + l;
            if (s > m) {
                float r = fast_exp(m - s);
                Z = Z * r + 1.0f;
                c = c * r;
                float cand = vv[l];
                if (cand > c || (cand == c && j < bi)) { c = cand; bi = j; }
                m = s;
            } else {
                float e = fast_exp(s - m);
                Z += e;
                float cand = e * vv[l];
                if (cand > c || (cand == c && j < bi)) { c = cand; bi = j; }
            }
        }
    }

    const unsigned full = 0xffffffffu;
    #pragma unroll
    for (int off = 16; off > 0; off >>= 1) {
        float m2 = __shfl_down_sync(full, m, off);
        float Z2 = __shfl_down_sync(full, Z, off);
        float c2 = __shfl_down_sync(full, c, off);
        int   b2 = __shfl_down_sync(full, bi, off);
        combine(m, Z, c, bi, m2, Z2, c2, b2);
    }

    __shared__ float sm[8], sz[8], sc[8];
    __shared__ int   sbuf[8];
    int wid = tid >> 5, lane = tid & 31;
    if (lane == 0) { sm[wid] = m; sz[wid] = Z; sc[wid] = c; sbuf[wid] = bi; }
    __syncthreads();
    if (tid == 0) {
        #pragma unroll
        for (int w = 1; w < 8; w++)
            combine(m, Z, c, bi, sm[w], sz[w], sc[w], sbuf[w]);
        out[row]         = c / Z;
        out[N_SEQ + row] = (float)bi;
    }
}

// ---------------- launch ------------------------------------------------------
extern "C" void kernel_launch(void* const* d_in, const int* in_sizes, int n_in,
                              void* d_out, int out_size)
{
    const float* x  = (const float*)d_in[0];
    const float* Wk = (const float*)d_in[1];
    const float* bk = (const float*)d_in[2];
    const float* Wv = (const float*)d_in[3];
    const float* bv = (const float*)d_in[4];
    // d_in[5]/d_in[6] (Wq,bq) are dead in the reference (x_q = x@Wv+bv)
    float* out = (float*)d_out;

    static bool attr_done = false;
    if (!attr_done) {
        cudaFuncSetAttribute(gemm3_kernel<0>, cudaFuncAttributeMaxDynamicSharedMemorySize, SMEM_BYTES);
        cudaFuncSetAttribute(gemm3_kernel<1>, cudaFuncAttributeMaxDynamicSharedMemorySize, SMEM_BYTES);
        cudaFuncSetAttribute(gemm3_kernel<2>, cudaFuncAttributeMaxDynamicSharedMemorySize, SMEM_BYTES);
        attr_done = true;
    }

    // 1) split x into bf16 hi/lo
    convert_x_kernel<<<8192, 256>>>(x);
    // 2) transpose+split weights
    dim3 tg(HALF_K / 32, SIZE_K / 32);
    transpose_split_kernel<0><<<tg, dim3(32, 8)>>>(Wk);
    transpose_split_kernel<1><<<tg, dim3(32, 8)>>>(Wv);
    // 3) projections + scores on HMMA tensor cores (3-term bf16 split)
    dim3 gproj(N_SEQ / BM, HALF_K / BN);
    dim3 gsc  (N_SEQ / BM, N_SEQ / BN);
    gemm3_kernel<0><<<gproj, GT, SMEM_BYTES>>>(bk);
    gemm3_kernel<1><<<gproj, GT, SMEM_BYTES>>>(bv);
    gemm3_kernel<2><<<gsc,   GT, SMEM_BYTES>>>(nullptr);
    // 4) softmax + elementwise V + row max/argmax
    softmax_combine_kernel<<<N_SEQ, 256>>>(out);
}

// round 4
// speedup vs baseline: 3.4381x; 1.0003x over previous
#include <cuda_runtime.h>
#include <cuda_bf16.h>
#include <math.h>
#include <stdint.h>

#define N_SEQ  4096
#define SIZE_K 8192
#define HALF_K 4096

#define BM   128
#define BN   128
#define BKC  64          // K elements per pipeline chunk (128 bytes bf16)
#define GT   256         // threads per GEMM CTA (8 warps)

// ---------------- scratch (static device globals; no runtime alloc) ----------
__device__ __nv_bfloat16 g_xh[(size_t)N_SEQ * SIZE_K];
__device__ __nv_bfloat16 g_xl[(size_t)N_SEQ * SIZE_K];
__device__ __nv_bfloat16 g_wkh[(size_t)HALF_K * SIZE_K];   // Wk^T hi  [4096,8192]
__device__ __nv_bfloat16 g_wkl[(size_t)HALF_K * SIZE_K];
__device__ __nv_bfloat16 g_wvh[(size_t)HALF_K * SIZE_K];
__device__ __nv_bfloat16 g_wvl[(size_t)HALF_K * SIZE_K];
__device__ __nv_bfloat16 g_kh[(size_t)N_SEQ * HALF_K];     // K split
__device__ __nv_bfloat16 g_kl[(size_t)N_SEQ * HALF_K];
__device__ __nv_bfloat16 g_vh[(size_t)N_SEQ * HALF_K];     // V split
__device__ __nv_bfloat16 g_vl[(size_t)N_SEQ * HALF_K];
__device__ float         g_v [(size_t)N_SEQ * HALF_K];     // V fp32
__device__ float         g_s [(size_t)N_SEQ * N_SEQ];      // scores fp32

// ---------------- PTX helpers (base sm_103 features only) --------------------
static __device__ __forceinline__ uint32_t smem_u32(const void* p) {
    uint32_t a;
    asm("{ .reg .u64 t; cvta.to.shared.u64 t, %1; cvt.u32.u64 %0, t; }" : "=r"(a) : "l"(p));
    return a;
}
static __device__ __forceinline__ void cp16(uint32_t s, const void* g) {
    asm volatile("cp.async.cg.shared.global [%0], [%1], 16;" :: "r"(s), "l"(g));
}
static __device__ __forceinline__ void cp_commit() {
    asm volatile("cp.async.commit_group;" ::: "memory");
}
template<int NP> static __device__ __forceinline__ void cp_wait() {
    asm volatile("cp.async.wait_group %0;" :: "n"(NP) : "memory");
}
static __device__ __forceinline__ void ldsm4(uint32_t* r, uint32_t addr) {
    asm volatile("ldmatrix.sync.aligned.m8n8.x4.shared.b16 {%0,%1,%2,%3}, [%4];"
        : "=r"(r[0]), "=r"(r[1]), "=r"(r[2]), "=r"(r[3]) : "r"(addr));
}
static __device__ __forceinline__ void mma16816(float* c, const uint32_t* a, const uint32_t* b) {
    asm volatile(
        "mma.sync.aligned.m16n8k16.row.col.f32.bf16.bf16.f32 "
        "{%0,%1,%2,%3}, {%4,%5,%6,%7}, {%8,%9}, {%0,%1,%2,%3};"
        : "+f"(c[0]), "+f"(c[1]), "+f"(c[2]), "+f"(c[3])
        : "r"(a[0]), "r"(a[1]), "r"(a[2]), "r"(a[3]), "r"(b[0]), "r"(b[1]));
}
static __device__ __forceinline__ void split2(float x0, float x1, uint32_t& h, uint32_t& l) {
    __nv_bfloat16 h0 = __float2bfloat16(x0), h1 = __float2bfloat16(x1);
    __nv_bfloat16 l0 = __float2bfloat16(x0 - __bfloat162float(h0));
    __nv_bfloat16 l1 = __float2bfloat16(x1 - __bfloat162float(h1));
    h = (uint32_t)__bfloat16_as_ushort(h0) | ((uint32_t)__bfloat16_as_ushort(h1) << 16);
    l = (uint32_t)__bfloat16_as_ushort(l0) | ((uint32_t)__bfloat16_as_ushort(l1) << 16);
}

// ---------------- convert / split kernels ------------------------------------
__global__ __launch_bounds__(256)
void convert_x_kernel(const float* __restrict__ x)
{
    const size_t total4 = (size_t)N_SEQ * SIZE_K / 4;
    __nv_bfloat162* xh2 = reinterpret_cast<__nv_bfloat162*>(g_xh);
    __nv_bfloat162* xl2 = reinterpret_cast<__nv_bfloat162*>(g_xl);
    for (size_t i = (size_t)blockIdx.x * blockDim.x + threadIdx.x; i < total4;
         i += (size_t)gridDim.x * blockDim.x) {
        float4 v = reinterpret_cast<const float4*>(x)[i];
        __nv_bfloat16 h0 = __float2bfloat16(v.x), h1 = __float2bfloat16(v.y);
        __nv_bfloat16 h2 = __float2bfloat16(v.z), h3 = __float2bfloat16(v.w);
        __nv_bfloat16 l0 = __float2bfloat16(v.x - __bfloat162float(h0));
        __nv_bfloat16 l1 = __float2bfloat16(v.y - __bfloat162float(h1));
        __nv_bfloat16 l2 = __float2bfloat16(v.z - __bfloat162float(h2));
        __nv_bfloat16 l3 = __float2bfloat16(v.w - __bfloat162float(h3));
        xh2[2 * i]     = __nv_bfloat162(h0, h1);
        xh2[2 * i + 1] = __nv_bfloat162(h2, h3);
        xl2[2 * i]     = __nv_bfloat162(l0, l1);
        xl2[2 * i + 1] = __nv_bfloat162(l2, l3);
    }
}

// W [SIZE_K, HALF_K] fp32 -> WT hi/lo [HALF_K, SIZE_K] bf16
template<int WSEL>
__global__ __launch_bounds__(256)
void transpose_split_kernel(const float* __restrict__ W)
{
    __nv_bfloat16* dh = (WSEL == 0) ? g_wkh : g_wvh;
    __nv_bfloat16* dl = (WSEL == 0) ? g_wkl : g_wvl;
    __shared__ float t[32][33];
    int n0 = blockIdx.x * 32;
    int k0 = blockIdx.y * 32;
    int tx = threadIdx.x, ty = threadIdx.y;   // block (32, 8)
    #pragma unroll
    for (int i = 0; i < 4; i++)
        t[ty + i * 8][tx] = W[(size_t)(k0 + ty + i * 8) * HALF_K + n0 + tx];
    __syncthreads();
    #pragma unroll
    for (int i = 0; i < 4; i++) {
        int n = n0 + ty + i * 8;
        int k = k0 + tx;
        float v = t[tx][ty + i * 8];
        __nv_bfloat16 h = __float2bfloat16(v);
        __nv_bfloat16 l = __float2bfloat16(v - __bfloat162float(h));
        dh[(size_t)n * SIZE_K + k] = h;
        dl[(size_t)n * SIZE_K + k] = l;
    }
}

// ---------------- HMMA split-bf16 GEMM ---------------------------------------
// MODE 0: K proj  (A=x, B=Wk^T, out: g_kh/g_kl,     bias=bk, K=8192)
// MODE 1: V proj  (A=x, B=Wv^T, out: g_v,g_vh/g_vl, bias=bv, K=8192)
// MODE 2: scores  (A=V, B=K,    out: g_s,           alpha=1/90, K=4096)
//
// smem stage (64 KB): Ah[128][64] | Al | Bh[128][64] | Bl, 16 KB each,
// 128B rows with xor swizzle. THREE stages, cp.async pipeline, 1 sync/chunk.
#define STG_BYTES 65536u
#define NSTG 3
#define SMEM_BYTES (NSTG * STG_BYTES)

template<int MODE>
__global__ __launch_bounds__(GT, 1)
void gemm3_kernel(const float* __restrict__ bias)
{
    const __nv_bfloat16 *Ah, *Al, *Bh, *Bl;
    int Ktot;
    if (MODE == 0)      { Ah = g_xh; Al = g_xl; Bh = g_wkh; Bl = g_wkl; Ktot = SIZE_K; }
    else if (MODE == 1) { Ah = g_xh; Al = g_xl; Bh = g_wvh; Bl = g_wvl; Ktot = SIZE_K; }
    else                { Ah = g_vh; Al = g_vl; Bh = g_kh;  Bl = g_kl;  Ktot = HALF_K; }

    extern __shared__ char smem[];
    const uint32_t sb = smem_u32(smem);
    const int tid  = threadIdx.x;
    const int wid  = tid >> 5;
    const int lane = tid & 31;
    const int wm   = wid & 3;     // warp row 0..3  (32 rows each)
    const int wn   = wid >> 2;    // warp col 0..1  (64 cols each)

    const int bm = blockIdx.x * BM;
    const int bn = blockIdx.y * BN;

    float acc[2][8][4];
    #pragma unroll
    for (int t = 0; t < 2; t++)
        #pragma unroll
        for (int n = 0; n < 8; n++)
            #pragma unroll
            for (int q = 0; q < 4; q++) acc[t][n][q] = 0.0f;

    const int nch = Ktot / BKC;

    auto load_chunk = [&](int ch) {
        const uint32_t stg = sb + (uint32_t)(ch % NSTG) * STG_BYTES;
        const size_t k0 = (size_t)ch * BKC;
        #pragma unroll
        for (int i = 0; i < 4; i++) {
            int pos = tid + i * GT;            // 0..1023
            int row = pos >> 3, seg = pos & 7;
            uint32_t soff = row * 128 + ((seg ^ (row & 7)) << 4);
            size_t ga = (size_t)(bm + row) * Ktot + k0 + seg * 8;
            size_t gb = (size_t)(bn + row) * Ktot + k0 + seg * 8;
            cp16(stg +      0 + soff, Ah + ga);
            cp16(stg + 16384u + soff, Al + ga);
            cp16(stg + 32768u + soff, Bh + gb);
            cp16(stg + 49152u + soff, Bl + gb);
        }
    };

    // fragment registers, double-buffered across k16 steps
    uint32_t afh[2][2][4], afl[2][2][4], bfh[2][4][4], bfl[2][4][4];

    auto frag_load = [&](uint32_t stg, int k16, int buf) {
        #pragma unroll
        for (int t = 0; t < 2; ++t) {
            int row = wm * 32 + t * 16 + (lane & 15);
            int seg = k16 * 2 + (lane >> 4);
            uint32_t off = row * 128 + ((seg ^ (row & 7)) << 4);
            ldsm4(afh[buf][t], stg + off);
            ldsm4(afl[buf][t], stg + 16384u + off);
        }
        #pragma unroll
        for (int p = 0; p < 4; ++p) {
            int row = wn * 64 + p * 16 + ((lane >> 4) << 3) + (lane & 7);
            int seg = k16 * 2 + ((lane >> 3) & 1);
            uint32_t off = row * 128 + ((seg ^ (row & 7)) << 4);
            ldsm4(bfh[buf][p], stg + 32768u + off);
            ldsm4(bfl[buf][p], stg + 49152u + off);
        }
    };

    // prologue: prefetch 2 chunks
    load_chunk(0); cp_commit();
    if (nch > 1) load_chunk(1);
    cp_commit();

    for (int ch = 0; ch < nch; ++ch) {
        cp_wait<1>();            // chunk ch resident
        __syncthreads();         // also: all warps done reading stage (ch+2)%3
        if (ch + 2 < nch) load_chunk(ch + 2);
        cp_commit();             // always commit (possibly empty) to keep counts

        const uint32_t stg = sb + (uint32_t)(ch % NSTG) * STG_BYTES;
        frag_load(stg, 0, 0);

        #pragma unroll
        for (int k16 = 0; k16 < 4; ++k16) {
            const int cur = k16 & 1, nxt = cur ^ 1;
            if (k16 < 3) frag_load(stg, k16 + 1, nxt);
            // term 1: hi*hi — 16 independent accumulators back-to-back
            #pragma unroll
            for (int t = 0; t < 2; ++t)
                #pragma unroll
                for (int nt = 0; nt < 8; ++nt)
                    mma16816(acc[t][nt], afh[cur][t], &bfh[cur][nt >> 1][(nt & 1) * 2]);
            // term 2: hi*lo
            #pragma unroll
            for (int t = 0; t < 2; ++t)
                #pragma unroll
                for (int nt = 0; nt < 8; ++nt)
                    mma16816(acc[t][nt], afh[cur][t], &bfl[cur][nt >> 1][(nt & 1) * 2]);
            // term 3: lo*hi
            #pragma unroll
            for (int t = 0; t < 2; ++t)
                #pragma unroll
                for (int nt = 0; nt < 8; ++nt)
                    mma16816(acc[t][nt], afl[cur][t], &bfh[cur][nt >> 1][(nt & 1) * 2]);
        }
    }

    // ---- epilogue: mma C frag: c0,c1 @ (row, col..col+1), c2,c3 @ (row+8)
    #pragma unroll
    for (int t = 0; t < 2; ++t) {
        #pragma unroll
        for (int nt = 0; nt < 8; ++nt) {
            float* c = acc[t][nt];
            const int n  = bn + wn * 64 + nt * 8 + (lane & 3) * 2;
            const int m0 = bm + wm * 32 + t * 16 + (lane >> 2);
            if (MODE == 2) {
                const float a = 1.0f / 90.0f;
                *(float2*)&g_s[(size_t)m0 * N_SEQ + n]       = make_float2(c[0] * a, c[1] * a);
                *(float2*)&g_s[(size_t)(m0 + 8) * N_SEQ + n] = make_float2(c[2] * a, c[3] * a);
            } else {
                float b0 = __ldg(&bias[n]), b1 = __ldg(&bias[n + 1]);
                float x0 = c[0] + b0, x1 = c[1] + b1;
                float y0 = c[2] + b0, y1 = c[3] + b1;
                if (MODE == 1) {
                    *(float2*)&g_v[(size_t)m0 * HALF_K + n]       = make_float2(x0, x1);
                    *(float2*)&g_v[(size_t)(m0 + 8) * HALF_K + n] = make_float2(y0, y1);
                }
                __nv_bfloat16* dsth = (MODE == 0) ? g_kh : g_vh;
                __nv_bfloat16* dstl = (MODE == 0) ? g_kl : g_vl;
                uint32_t h, l;
                split2(x0, x1, h, l);
                *(uint32_t*)&dsth[(size_t)m0 * HALF_K + n] = h;
                *(uint32_t*)&dstl[(size_t)m0 * HALF_K + n] = l;
                split2(y0, y1, h, l);
                *(uint32_t*)&dsth[(size_t)(m0 + 8) * HALF_K + n] = h;
                *(uint32_t*)&dstl[(size_t)(m0 + 8) * HALF_K + n] = l;
            }
        }
    }
}

// ---------------- fast exp on the FMA pipe (no MUFU) -------------------------
__device__ __forceinline__ float fast_exp(float x) {
    x = fmaxf(x, -87.0f);
    const float L2E = 1.4426950408889634f;
    float t = x * L2E;
    float z = t + 12582912.0f;
    float n = z - 12582912.0f;
    float f = t - n;
    int   i = __float_as_int(z) - 0x4B400000;
    float p = 1.3333558146e-3f;
    p = fmaf(p, f, 9.6181291076e-3f);
    p = fmaf(p, f, 5.5504108665e-2f);
    p = fmaf(p, f, 2.4022650696e-1f);
    p = fmaf(p, f, 6.9314718056e-1f);
    p = fmaf(p, f, 1.0f);
    float sc = __int_as_float((i + 127) << 23);
    return p * sc;
}

__device__ __forceinline__ void combine(float& m, float& Z, float& c, int& bi,
                                        float m2, float Z2, float c2, int bi2) {
    float M  = fmaxf(m, m2);
    float r1 = fast_exp(m  - M);
    float r2 = fast_exp(m2 - M);
    Z = Z * r1 + Z2 * r2;
    float ca = c  * r1;
    float cb = c2 * r2;
    if (cb > ca || (cb == ca && bi2 < bi)) { c = cb; bi = bi2; }
    else                                   { c = ca; }
    m = M;
}

__global__ __launch_bounds__(256)
void softmax_combine_kernel(float* __restrict__ out)
{
    const int row = blockIdx.x;
    const float4* __restrict__ S4 = (const float4*)(g_s + (size_t)row * N_SEQ);
    const float4* __restrict__ V4 = (const float4*)(g_v + (size_t)row * N_SEQ);
    const int tid = threadIdx.x;

    float m = -INFINITY, Z = 0.0f, c = -INFINITY;
    int bi = 0;

    #pragma unroll
    for (int it = 0; it < 4; it++) {
        int q = tid + it * 256;
        float4 s4 = S4[q];
        float4 v4 = V4[q];
        float ss[4] = {s4.x, s4.y, s4.z, s4.w};
        float vv[4] = {v4.x, v4.y, v4.z, v4.w};
        #pragma unroll
        for (int l = 0; l < 4; l++) {
            float s = ss[l];
            int   j = q * 4 + l;
            if (s > m) {
                float r = fast_exp(m - s);
                Z = Z * r + 1.0f;
                c = c * r;
                float cand = vv[l];
                if (cand > c || (cand == c && j < bi)) { c = cand; bi = j; }
                m = s;
            } else {
                float e = fast_exp(s - m);
                Z += e;
                float cand = e * vv[l];
                if (cand > c || (cand == c && j < bi)) { c = cand; bi = j; }
            }
        }
    }

    const unsigned full = 0xffffffffu;
    #pragma unroll
    for (int off = 16; off > 0; off >>= 1) {
        float m2 = __shfl_down_sync(full, m, off);
        float Z2 = __shfl_down_sync(full, Z, off);
        float c2 = __shfl_down_sync(full, c, off);
        int   b2 = __shfl_down_sync(full, bi, off);
        combine(m, Z, c, bi, m2, Z2, c2, b2);
    }

    __shared__ float sm[8], sz[8], sc[8];
    __shared__ int   sbuf[8];
    int wid = tid >> 5, lane = tid & 31;
    if (lane == 0) { sm[wid] = m; sz[wid] = Z; sc[wid] = c; sbuf[wid] = bi; }
    __syncthreads();
    if (tid == 0) {
        #pragma unroll
        for (int w = 1; w < 8; w++)
            combine(m, Z, c, bi, sm[w], sz[w], sc[w], sbuf[w]);
        out[row]         = c / Z;
        out[N_SEQ + row] = (float)bi;
    }
}

// ---------------- launch ------------------------------------------------------
extern "C" void kernel_launch(void* const* d_in, const int* in_sizes, int n_in,
                              void* d_out, int out_size)
{
    const float* x  = (const float*)d_in[0];
    const float* Wk = (const float*)d_in[1];
    const float* bk = (const float*)d_in[2];
    const float* Wv = (const float*)d_in[3];
    const float* bv = (const float*)d_in[4];
    // d_in[5]/d_in[6] (Wq,bq) are dead in the reference (x_q = x@Wv+bv)
    float* out = (float*)d_out;

    static bool attr_done = false;
    if (!attr_done) {
        cudaFuncSetAttribute(gemm3_kernel<0>, cudaFuncAttributeMaxDynamicSharedMemorySize, SMEM_BYTES);
        cudaFuncSetAttribute(gemm3_kernel<1>, cudaFuncAttributeMaxDynamicSharedMemorySize, SMEM_BYTES);
        cudaFuncSetAttribute(gemm3_kernel<2>, cudaFuncAttributeMaxDynamicSharedMemorySize, SMEM_BYTES);
        attr_done = true;
    }

    // 1) split x into bf16 hi/lo
    convert_x_kernel<<<8192, 256>>>(x);
    // 2) transpose+split weights
    dim3 tg(HALF_K / 32, SIZE_K / 32);
    transpose_split_kernel<0><<<tg, dim3(32, 8)>>>(Wk);
    transpose_split_kernel<1><<<tg, dim3(32, 8)>>>(Wv);
    // 3) projections + scores on HMMA tensor cores (3-term bf16 split)
    dim3 gproj(N_SEQ / BM, HALF_K / BN);
    dim3 gsc  (N_SEQ / BM, N_SEQ / BN);
    gemm3_kernel<0><<<gproj, GT, SMEM_BYTES>>>(bk);
    gemm3_kernel<1><<<gproj, GT, SMEM_BYTES>>>(bv);
    gemm3_kernel<2><<<gsc,   GT, SMEM_BYTES>>>(nullptr);
    // 4) softmax + elementwise V + row max/argmax
    softmax_combine_kernel<<<N_SEQ, 256>>>(out);
}